// round 10
// baseline (speedup 1.0000x reference)
#include <cuda_runtime.h>
#include <cuda_bf16.h>

#define LEN 8192      // L
#define NROWS 8192    // B*C
#define CHUNK 256     // elements per warp-chunk (8 per lane)
#define NCHUNK (LEN / CHUNK)   // 32

// Single-kernel warp-autonomous solver. No barriers, no shared memory, no
// device scratch, no atomics: static near-perfectly-balanced row assignment
// (host sizes the grid so every warp gets <=2 rows).
//
// Transformed recurrence: y[i] = ap[i]*y[i+1] + z[i],  x[i] = rinv[i]*y[i]
//   ap[i] = -sup[i+1]/diag[i+1]  (ap[L-1] = 0),  rinv[i] = 1/diag[i]
// The Cholesky recursion is a contraction: ap/rinv are fp32-constant for
// i in [~64, L-2] (validated: rel_err unchanged vs exact). Middle chunks use
// two scalar constants; boundary chunks (0, 31) compute exact coefficients
// inline from diag/sup.
//
// Memory pipeline: register-prefetch 1 chunk ahead (consumes 8 regs) +
// L2 prefetch 2 chunks ahead (zero regs) so LDGs complete at L2 latency.
__global__ __launch_bounds__(896, 1) void ou_solve_kernel(const float* __restrict__ z,
                                                          const float* __restrict__ diag,
                                                          const float* __restrict__ sup,
                                                          float* __restrict__ x) {
    const int lane = threadIdx.x & 31;
    const int warp = threadIdx.x >> 5;
    const int wpc  = blockDim.x >> 5;            // warps per CTA
    const int gw   = blockIdx.x * wpc + warp;    // global warp id
    const int W    = gridDim.x * wpc;            // total warps

    // Converged mid-array constants (one L1-resident read each).
    const float rinv_c = 1.0f / diag[LEN / 2];
    const float ap_c   = -sup[LEN / 2 + 1] / diag[LEN / 2 + 1];
    float p2 = ap_c * ap_c;
    float p4 = p2 * p2;
    const float Aseg_c = p4 * p4;                // ap_c^8

    // Loop-invariant A-side of the warp reverse scan.
    float As0, As1, As2, As3, As4, sA_f;
    {
        float sA = Aseg_c;
        As0 = sA; { float A2 = __shfl_down_sync(0xffffffffu, sA, 1);  if (lane + 1  < 32) sA *= A2; }
        As1 = sA; { float A2 = __shfl_down_sync(0xffffffffu, sA, 2);  if (lane + 2  < 32) sA *= A2; }
        As2 = sA; { float A2 = __shfl_down_sync(0xffffffffu, sA, 4);  if (lane + 4  < 32) sA *= A2; }
        As3 = sA; { float A2 = __shfl_down_sync(0xffffffffu, sA, 8);  if (lane + 8  < 32) sA *= A2; }
        As4 = sA; { float A2 = __shfl_down_sync(0xffffffffu, sA, 16); if (lane + 16 < 32) sA *= A2; }
        sA_f = sA;
    }

    int row = gw;
    if (row >= NROWS) return;

    // Prefetch the first row's top chunk into registers, and the next chunk
    // into L2.
    float4 nz0, nz1;
    {
        const float* p = z + (size_t)row * LEN + (NCHUNK - 1) * CHUNK + lane * 8;
        nz0 = __ldcs((const float4*)(p));
        nz1 = __ldcs((const float4*)(p + 4));
        if ((lane & 3) == 0) {
            const float* pp = z + (size_t)row * LEN + (NCHUNK - 2) * CHUNK + lane * 8;
            asm volatile("prefetch.global.L2 [%0];" :: "l"(pp));
        }
    }

    while (row < NROWS) {
        const int nextrow = row + W;
        const float* zr = z + (size_t)row * LEN;
        float*       xr = x + (size_t)row * LEN;

        float carry = 0.0f;   // y at element (c+1)*CHUNK; 0 beyond row end

        #pragma unroll 1
        for (int c = NCHUNK - 1; c >= 0; --c) {
            float4 u0 = nz0, u1 = nz1;
            const int off = c * CHUNK + lane * 8;

            // Register-prefetch next chunk (or next row's top chunk).
            if (c > 0) {
                const float* p = zr + (c - 1) * CHUNK + lane * 8;
                nz0 = __ldcs((const float4*)(p));
                nz1 = __ldcs((const float4*)(p + 4));
            } else if (nextrow < NROWS) {
                const float* p = z + (size_t)nextrow * LEN + (NCHUNK - 1) * CHUNK + lane * 8;
                nz0 = __ldcs((const float4*)(p));
                nz1 = __ldcs((const float4*)(p + 4));
            }

            // L2-prefetch two chunks ahead (8 lanes cover the 8 x 128B lines
            // of the 1KB chunk; zero register cost).
            if ((lane & 3) == 0) {
                if (c > 1) {
                    const float* pp = zr + (c - 2) * CHUNK + lane * 8;
                    asm volatile("prefetch.global.L2 [%0];" :: "l"(pp));
                } else if (nextrow < NROWS) {
                    // c==1 -> next row chunk 31; c==0 -> next row chunk 30.
                    const float* pp = z + (size_t)nextrow * LEN
                                        + (NCHUNK - 2 + c) * CHUNK + lane * 8;
                    asm volatile("prefetch.global.L2 [%0];" :: "l"(pp));
                }
            }

            if (c != 0 && c != NCHUNK - 1) {
                // ---------- FAST PATH: scalar coefficients ----------
                float B = u1.w;
                B = fmaf(ap_c, B, u1.z);
                B = fmaf(ap_c, B, u1.y);
                B = fmaf(ap_c, B, u1.x);
                B = fmaf(ap_c, B, u0.w);
                B = fmaf(ap_c, B, u0.z);
                B = fmaf(ap_c, B, u0.y);
                B = fmaf(ap_c, B, u0.x);

                float sB = B;
                { float B2 = __shfl_down_sync(0xffffffffu, sB, 1);  if (lane + 1  < 32) sB = fmaf(As0, B2, sB); }
                { float B2 = __shfl_down_sync(0xffffffffu, sB, 2);  if (lane + 2  < 32) sB = fmaf(As1, B2, sB); }
                { float B2 = __shfl_down_sync(0xffffffffu, sB, 4);  if (lane + 4  < 32) sB = fmaf(As2, B2, sB); }
                { float B2 = __shfl_down_sync(0xffffffffu, sB, 8);  if (lane + 8  < 32) sB = fmaf(As3, B2, sB); }
                { float B2 = __shfl_down_sync(0xffffffffu, sB, 16); if (lane + 16 < 32) sB = fmaf(As4, B2, sB); }

                float Bf = fmaf(sA_f, carry, sB);
                float y = __shfl_down_sync(0xffffffffu, Bf, 1);
                if (lane == 31) y = carry;
                carry = __shfl_sync(0xffffffffu, Bf, 0);

                y = fmaf(ap_c, y, u1.w); u1.w = rinv_c * y;
                y = fmaf(ap_c, y, u1.z); u1.z = rinv_c * y;
                y = fmaf(ap_c, y, u1.y); u1.y = rinv_c * y;
                y = fmaf(ap_c, y, u1.x); u1.x = rinv_c * y;
                y = fmaf(ap_c, y, u0.w); u0.w = rinv_c * y;
                y = fmaf(ap_c, y, u0.z); u0.z = rinv_c * y;
                y = fmaf(ap_c, y, u0.y); u0.y = rinv_c * y;
                y = fmaf(ap_c, y, u0.x); u0.x = rinv_c * y;
            } else {
                // ---------- BOUNDARY PATH: exact coefficients inline ----------
                const float4 d0 = *(const float4*)(diag + off);
                const float4 d1 = *(const float4*)(diag + off + 4);
                const float4 s0 = *(const float4*)(sup + off);
                const float4 s1 = *(const float4*)(sup + off + 4);
                float4 r0, r1;
                r0.x = 1.0f / d0.x; r0.y = 1.0f / d0.y; r0.z = 1.0f / d0.z; r0.w = 1.0f / d0.w;
                r1.x = 1.0f / d1.x; r1.y = 1.0f / d1.y; r1.z = 1.0f / d1.z; r1.w = 1.0f / d1.w;
                // ap[i] = -sup[i+1]*rinv[i+1]
                float4 a0, a1;
                a0.x = -s0.y * r0.y; a0.y = -s0.z * r0.z; a0.z = -s0.w * r0.w; a0.w = -s1.x * r1.x;
                a1.x = -s1.y * r1.y; a1.y = -s1.z * r1.z; a1.z = -s1.w * r1.w;
                float t = -s0.x * r0.x;                    // next lane's first ap source
                a1.w = __shfl_down_sync(0xffffffffu, t, 1);
                if (lane == 31) a1.w = (c == 0) ? ap_c : 0.0f;

                float B = u1.w;
                B = fmaf(a1.z, B, u1.z);
                B = fmaf(a1.y, B, u1.y);
                B = fmaf(a1.x, B, u1.x);
                B = fmaf(a0.w, B, u0.w);
                B = fmaf(a0.z, B, u0.z);
                B = fmaf(a0.y, B, u0.y);
                B = fmaf(a0.x, B, u0.x);
                float Aseg = ((a1.w * a1.z) * (a1.y * a1.x)) *
                             ((a0.w * a0.z) * (a0.y * a0.x));

                float sA = Aseg, sB = B;
                #pragma unroll
                for (int d = 1; d < 32; d <<= 1) {
                    float A2 = __shfl_down_sync(0xffffffffu, sA, d);
                    float B2 = __shfl_down_sync(0xffffffffu, sB, d);
                    if (lane + d < 32) {
                        sB = fmaf(sA, B2, sB);
                        sA *= A2;
                    }
                }

                float Bf = fmaf(sA, carry, sB);
                float y = __shfl_down_sync(0xffffffffu, Bf, 1);
                if (lane == 31) y = carry;
                carry = __shfl_sync(0xffffffffu, Bf, 0);

                y = fmaf(a1.w, y, u1.w); u1.w = r1.w * y;
                y = fmaf(a1.z, y, u1.z); u1.z = r1.z * y;
                y = fmaf(a1.y, y, u1.y); u1.y = r1.y * y;
                y = fmaf(a1.x, y, u1.x); u1.x = r1.x * y;
                y = fmaf(a0.w, y, u0.w); u0.w = r0.w * y;
                y = fmaf(a0.z, y, u0.z); u0.z = r0.z * y;
                y = fmaf(a0.y, y, u0.y); u0.y = r0.y * y;
                y = fmaf(a0.x, y, u0.x); u0.x = r0.x * y;
            }

            __stcs((float4*)(xr + off),     u0);
            __stcs((float4*)(xr + off + 4), u1);
        }
        row = nextrow;
    }
}

extern "C" void kernel_launch(void* const* d_in, const int* in_sizes, int n_in,
                              void* d_out, int out_size) {
    const float* normal_samples = (const float*)d_in[0];  // (32, 256, 8192) f32
    const float* diag           = (const float*)d_in[1];  // (8192,) f32
    const float* sup            = (const float*)d_in[2];  // (8192,) f32
    float* out = (float*)d_out;

    (void)in_sizes; (void)n_in; (void)out_size;

    int sm_count = 148;
    cudaDeviceGetAttribute(&sm_count, cudaDevAttrMultiProcessorCount, 0);

    // warps_per_CTA = ceil((NROWS/2) / sm_count): every warp gets <=2 rows
    // (on 152 SMs: 4104 warps; 4088 do 2 rows, 16 do 1 -> 99.8% balance).
    int wpc = (NROWS / 2 + sm_count - 1) / sm_count;
    if (wpc > 28) wpc = 28;   // stay under __launch_bounds__(896)
    ou_solve_kernel<<<sm_count, wpc * 32>>>(normal_samples, diag, sup, out);
}

// round 11
// speedup vs baseline: 1.1673x; 1.1673x over previous
#include <cuda_runtime.h>
#include <cuda_bf16.h>

#define LEN 8192      // L
#define NROWS 8192    // B*C
#define CHUNK 256     // elements per warp-chunk (8 per lane)
#define NCHUNK (LEN / CHUNK)   // 32

// Single-kernel warp-autonomous solver (R9 base: best = 90.1us, DRAM 72%).
// No barriers, no shared memory, no atomics, no L2 prefetch (regressed 2x).
// Static near-perfectly-balanced row assignment: every warp gets <=2 rows.
//
// Transformed recurrence: y[i] = ap[i]*y[i+1] + z[i],  x[i] = rinv[i]*y[i]
//   ap[i] = -sup[i+1]/diag[i+1]  (ap[L-1] = 0),  rinv[i] = 1/diag[i]
// Cholesky recursion is a contraction: ap/rinv are fp32-constant for
// i in [~64, L-2] (validated). Steady-state chunks use two scalar constants
// and a precomputed scan A-side; boundary chunks 31 and 0 are PEELED out of
// the loop and use exact coefficients computed inline from diag/sup.
__global__ __launch_bounds__(896, 1) void ou_solve_kernel(const float* __restrict__ z,
                                                          const float* __restrict__ diag,
                                                          const float* __restrict__ sup,
                                                          float* __restrict__ x) {
    const int lane = threadIdx.x & 31;
    const int warp = threadIdx.x >> 5;
    const int wpc  = blockDim.x >> 5;            // warps per CTA
    const int gw   = blockIdx.x * wpc + warp;    // global warp id
    const int W    = gridDim.x * wpc;            // total warps

    // Converged mid-array constants.
    const float rinv_c = 1.0f / diag[LEN / 2];
    const float ap_c   = -sup[LEN / 2 + 1] / diag[LEN / 2 + 1];
    float p2 = ap_c * ap_c;
    float p4 = p2 * p2;
    const float Aseg_c = p4 * p4;                // ap_c^8

    // Loop-invariant A-side of the warp reverse scan.
    float As0, As1, As2, As3, As4, sA_f;
    {
        float sA = Aseg_c;
        As0 = sA; { float A2 = __shfl_down_sync(0xffffffffu, sA, 1);  if (lane + 1  < 32) sA *= A2; }
        As1 = sA; { float A2 = __shfl_down_sync(0xffffffffu, sA, 2);  if (lane + 2  < 32) sA *= A2; }
        As2 = sA; { float A2 = __shfl_down_sync(0xffffffffu, sA, 4);  if (lane + 4  < 32) sA *= A2; }
        As3 = sA; { float A2 = __shfl_down_sync(0xffffffffu, sA, 8);  if (lane + 8  < 32) sA *= A2; }
        As4 = sA; { float A2 = __shfl_down_sync(0xffffffffu, sA, 16); if (lane + 16 < 32) sA *= A2; }
        sA_f = sA;
    }

    int row = gw;
    if (row >= NROWS) return;

    // Prefetch the first row's top chunk into registers.
    float4 nz0, nz1;
    {
        const float* p = z + (size_t)row * LEN + (NCHUNK - 1) * CHUNK + lane * 8;
        nz0 = __ldcs((const float4*)(p));
        nz1 = __ldcs((const float4*)(p + 4));
    }

    while (row < NROWS) {
        const int nextrow = row + W;
        const float* zr = z + (size_t)row * LEN;
        float*       xr = x + (size_t)row * LEN;

        float carry = 0.0f;

        // ================= PEELED chunk 31 (exact tail coefficients) =======
        {
            const int c = NCHUNK - 1;
            float4 u0 = nz0, u1 = nz1;
            const int off = c * CHUNK + lane * 8;
            // Prefetch chunk 30.
            {
                const float* p = zr + (c - 1) * CHUNK + lane * 8;
                nz0 = __ldcs((const float4*)(p));
                nz1 = __ldcs((const float4*)(p + 4));
            }

            const float4 d0 = *(const float4*)(diag + off);
            const float4 d1 = *(const float4*)(diag + off + 4);
            const float4 s0 = *(const float4*)(sup + off);
            const float4 s1 = *(const float4*)(sup + off + 4);
            float4 r0, r1;
            r0.x = 1.0f / d0.x; r0.y = 1.0f / d0.y; r0.z = 1.0f / d0.z; r0.w = 1.0f / d0.w;
            r1.x = 1.0f / d1.x; r1.y = 1.0f / d1.y; r1.z = 1.0f / d1.z; r1.w = 1.0f / d1.w;
            float4 a0, a1;
            a0.x = -s0.y * r0.y; a0.y = -s0.z * r0.z; a0.z = -s0.w * r0.w; a0.w = -s1.x * r1.x;
            a1.x = -s1.y * r1.y; a1.y = -s1.z * r1.z; a1.z = -s1.w * r1.w;
            float t = -s0.x * r0.x;
            a1.w = __shfl_down_sync(0xffffffffu, t, 1);
            if (lane == 31) a1.w = 0.0f;   // i = L-1: no successor

            float B = u1.w;
            B = fmaf(a1.z, B, u1.z);
            B = fmaf(a1.y, B, u1.y);
            B = fmaf(a1.x, B, u1.x);
            B = fmaf(a0.w, B, u0.w);
            B = fmaf(a0.z, B, u0.z);
            B = fmaf(a0.y, B, u0.y);
            B = fmaf(a0.x, B, u0.x);
            float Aseg = ((a1.w * a1.z) * (a1.y * a1.x)) *
                         ((a0.w * a0.z) * (a0.y * a0.x));

            float sA = Aseg, sB = B;
            #pragma unroll
            for (int d = 1; d < 32; d <<= 1) {
                float A2 = __shfl_down_sync(0xffffffffu, sA, d);
                float B2 = __shfl_down_sync(0xffffffffu, sB, d);
                if (lane + d < 32) {
                    sB = fmaf(sA, B2, sB);
                    sA *= A2;
                }
            }

            float Bf = fmaf(sA, carry, sB);
            float y = __shfl_down_sync(0xffffffffu, Bf, 1);
            if (lane == 31) y = carry;
            carry = __shfl_sync(0xffffffffu, Bf, 0);

            y = fmaf(a1.w, y, u1.w); u1.w = r1.w * y;
            y = fmaf(a1.z, y, u1.z); u1.z = r1.z * y;
            y = fmaf(a1.y, y, u1.y); u1.y = r1.y * y;
            y = fmaf(a1.x, y, u1.x); u1.x = r1.x * y;
            y = fmaf(a0.w, y, u0.w); u0.w = r0.w * y;
            y = fmaf(a0.z, y, u0.z); u0.z = r0.z * y;
            y = fmaf(a0.y, y, u0.y); u0.y = r0.y * y;
            y = fmaf(a0.x, y, u0.x); u0.x = r0.x * y;

            __stcs((float4*)(xr + off),     u0);
            __stcs((float4*)(xr + off + 4), u1);
        }

        // ================= STEADY STATE: chunks 30..1, pure fast path ======
        #pragma unroll 1
        for (int c = NCHUNK - 2; c >= 1; --c) {
            float4 u0 = nz0, u1 = nz1;
            const int off = c * CHUNK + lane * 8;

            // Unconditional in-row prefetch (c-1 >= 0 always here).
            {
                const float* p = zr + (c - 1) * CHUNK + lane * 8;
                nz0 = __ldcs((const float4*)(p));
                nz1 = __ldcs((const float4*)(p + 4));
            }

            float B = u1.w;
            B = fmaf(ap_c, B, u1.z);
            B = fmaf(ap_c, B, u1.y);
            B = fmaf(ap_c, B, u1.x);
            B = fmaf(ap_c, B, u0.w);
            B = fmaf(ap_c, B, u0.z);
            B = fmaf(ap_c, B, u0.y);
            B = fmaf(ap_c, B, u0.x);

            float sB = B;
            { float B2 = __shfl_down_sync(0xffffffffu, sB, 1);  if (lane + 1  < 32) sB = fmaf(As0, B2, sB); }
            { float B2 = __shfl_down_sync(0xffffffffu, sB, 2);  if (lane + 2  < 32) sB = fmaf(As1, B2, sB); }
            { float B2 = __shfl_down_sync(0xffffffffu, sB, 4);  if (lane + 4  < 32) sB = fmaf(As2, B2, sB); }
            { float B2 = __shfl_down_sync(0xffffffffu, sB, 8);  if (lane + 8  < 32) sB = fmaf(As3, B2, sB); }
            { float B2 = __shfl_down_sync(0xffffffffu, sB, 16); if (lane + 16 < 32) sB = fmaf(As4, B2, sB); }

            float Bf = fmaf(sA_f, carry, sB);
            float y = __shfl_down_sync(0xffffffffu, Bf, 1);
            if (lane == 31) y = carry;
            carry = __shfl_sync(0xffffffffu, Bf, 0);

            y = fmaf(ap_c, y, u1.w); u1.w = rinv_c * y;
            y = fmaf(ap_c, y, u1.z); u1.z = rinv_c * y;
            y = fmaf(ap_c, y, u1.y); u1.y = rinv_c * y;
            y = fmaf(ap_c, y, u1.x); u1.x = rinv_c * y;
            y = fmaf(ap_c, y, u0.w); u0.w = rinv_c * y;
            y = fmaf(ap_c, y, u0.z); u0.z = rinv_c * y;
            y = fmaf(ap_c, y, u0.y); u0.y = rinv_c * y;
            y = fmaf(ap_c, y, u0.x); u0.x = rinv_c * y;

            __stcs((float4*)(xr + off),     u0);
            __stcs((float4*)(xr + off + 4), u1);
        }

        // ================= PEELED chunk 0 (exact head coefficients) ========
        {
            float4 u0 = nz0, u1 = nz1;
            const int off = lane * 8;
            // Prefetch next row's top chunk.
            if (nextrow < NROWS) {
                const float* p = z + (size_t)nextrow * LEN + (NCHUNK - 1) * CHUNK + lane * 8;
                nz0 = __ldcs((const float4*)(p));
                nz1 = __ldcs((const float4*)(p + 4));
            }

            const float4 d0 = *(const float4*)(diag + off);
            const float4 d1 = *(const float4*)(diag + off + 4);
            const float4 s0 = *(const float4*)(sup + off);
            const float4 s1 = *(const float4*)(sup + off + 4);
            float4 r0, r1;
            r0.x = 1.0f / d0.x; r0.y = 1.0f / d0.y; r0.z = 1.0f / d0.z; r0.w = 1.0f / d0.w;
            r1.x = 1.0f / d1.x; r1.y = 1.0f / d1.y; r1.z = 1.0f / d1.z; r1.w = 1.0f / d1.w;
            float4 a0, a1;
            a0.x = -s0.y * r0.y; a0.y = -s0.z * r0.z; a0.z = -s0.w * r0.w; a0.w = -s1.x * r1.x;
            a1.x = -s1.y * r1.y; a1.y = -s1.z * r1.z; a1.z = -s1.w * r1.w;
            float t = -s0.x * r0.x;
            a1.w = __shfl_down_sync(0xffffffffu, t, 1);
            if (lane == 31) a1.w = ap_c;   // i = 255: converged region

            float B = u1.w;
            B = fmaf(a1.z, B, u1.z);
            B = fmaf(a1.y, B, u1.y);
            B = fmaf(a1.x, B, u1.x);
            B = fmaf(a0.w, B, u0.w);
            B = fmaf(a0.z, B, u0.z);
            B = fmaf(a0.y, B, u0.y);
            B = fmaf(a0.x, B, u0.x);
            float Aseg = ((a1.w * a1.z) * (a1.y * a1.x)) *
                         ((a0.w * a0.z) * (a0.y * a0.x));

            float sA = Aseg, sB = B;
            #pragma unroll
            for (int d = 1; d < 32; d <<= 1) {
                float A2 = __shfl_down_sync(0xffffffffu, sA, d);
                float B2 = __shfl_down_sync(0xffffffffu, sB, d);
                if (lane + d < 32) {
                    sB = fmaf(sA, B2, sB);
                    sA *= A2;
                }
            }

            float Bf = fmaf(sA, carry, sB);
            float y = __shfl_down_sync(0xffffffffu, Bf, 1);
            if (lane == 31) y = carry;

            y = fmaf(a1.w, y, u1.w); u1.w = r1.w * y;
            y = fmaf(a1.z, y, u1.z); u1.z = r1.z * y;
            y = fmaf(a1.y, y, u1.y); u1.y = r1.y * y;
            y = fmaf(a1.x, y, u1.x); u1.x = r1.x * y;
            y = fmaf(a0.w, y, u0.w); u0.w = r0.w * y;
            y = fmaf(a0.z, y, u0.z); u0.z = r0.z * y;
            y = fmaf(a0.y, y, u0.y); u0.y = r0.y * y;
            y = fmaf(a0.x, y, u0.x); u0.x = r0.x * y;

            __stcs((float4*)(xr + off),     u0);
            __stcs((float4*)(xr + off + 4), u1);
        }

        row = nextrow;
    }
}

extern "C" void kernel_launch(void* const* d_in, const int* in_sizes, int n_in,
                              void* d_out, int out_size) {
    const float* normal_samples = (const float*)d_in[0];  // (32, 256, 8192) f32
    const float* diag           = (const float*)d_in[1];  // (8192,) f32
    const float* sup            = (const float*)d_in[2];  // (8192,) f32
    float* out = (float*)d_out;

    (void)in_sizes; (void)n_in; (void)out_size;

    int sm_count = 148;
    cudaDeviceGetAttribute(&sm_count, cudaDevAttrMultiProcessorCount, 0);

    // warps_per_CTA = ceil((NROWS/2) / sm_count): every warp gets <=2 rows
    // (on 152 SMs: 4104 warps; 4088 do 2 rows, 16 do 1 -> 99.8% balance).
    int wpc = (NROWS / 2 + sm_count - 1) / sm_count;
    if (wpc > 28) wpc = 28;   // stay under __launch_bounds__(896)
    ou_solve_kernel<<<sm_count, wpc * 32>>>(normal_samples, diag, sup, out);
}